// round 1
// baseline (speedup 1.0000x reference)
#include <cuda_runtime.h>
#include <cstdint>

// Problem constants (fixed by the reference):
//   B=4, S=4096, D=2048, E=8, T=B*S=16384, C=T/E*1.25=2560, EC=E*C=20480
#define D_DIM   2048
#define T_TOK   16384
#define EC_ROWS 20480

// One block per candidate output row. Blocks [0, EC): expert rows scattered to
// token rows (skip padding rows with scatter_idx == T). Blocks [EC, EC+T):
// dropped-token fallback rows (copy x, factor 1). Every output row written
// exactly once; writer sets are disjoint, so a single kernel is safe.
__global__ __launch_bounds__(256) void moe_combine_kernel(
    const float* __restrict__ expert_outputs,   // [EC, D]
    const float* __restrict__ x,                // [T, D]
    const float* __restrict__ route_prob_max,   // [T]
    const int*   __restrict__ scatter_idx,      // [EC]
    const unsigned char* __restrict__ dropped,  // [T] bool
    float* __restrict__ out)                    // [T, D]
{
    const int bid = blockIdx.x;

    const float4* __restrict__ src4;
    float4* __restrict__ dst4;
    float factor;

    if (bid < EC_ROWS) {
        const int r = scatter_idx[bid];
        if (r >= T_TOK) return;                 // padding slot
        factor = route_prob_max[r];
        src4 = reinterpret_cast<const float4*>(expert_outputs + (size_t)bid * D_DIM);
        dst4 = reinterpret_cast<float4*>(out + (size_t)r * D_DIM);
    } else {
        const int t = bid - EC_ROWS;
        if (!dropped[t]) return;                // handled by scatter path
        factor = 1.0f;
        src4 = reinterpret_cast<const float4*>(x + (size_t)t * D_DIM);
        dst4 = reinterpret_cast<float4*>(out + (size_t)t * D_DIM);
    }

    // D=2048 floats = 512 float4; 256 threads * 2 float4 each.
    const int tid = threadIdx.x;
    float4 a = src4[tid];
    float4 b = src4[tid + 256];
    a.x *= factor; a.y *= factor; a.z *= factor; a.w *= factor;
    b.x *= factor; b.y *= factor; b.z *= factor; b.w *= factor;
    dst4[tid]       = a;
    dst4[tid + 256] = b;
}

extern "C" void kernel_launch(void* const* d_in, const int* in_sizes, int n_in,
                              void* d_out, int out_size) {
    const float*         expert_outputs = (const float*)d_in[0];
    const float*         x              = (const float*)d_in[1];
    const float*         route_prob_max = (const float*)d_in[2];
    const int*           scatter_idx    = (const int*)d_in[3];
    const unsigned char* dropped        = (const unsigned char*)d_in[4];
    float* out = (float*)d_out;

    moe_combine_kernel<<<EC_ROWS + T_TOK, 256>>>(
        expert_outputs, x, route_prob_max, scatter_idx, dropped, out);
}

// round 2
// speedup vs baseline: 1.1390x; 1.1390x over previous
#include <cuda_runtime.h>
#include <cstdint>

// Problem constants (fixed by the reference):
//   B=4, S=4096, D=2048, E=8, T=B*S=16384, C=T/E*1.25=2560, EC=E*C=20480
#define D_DIM   2048
#define T_TOK   16384
#define EC_ROWS 20480

// Per-token work descriptor: .x = source expert row (or -1 if none),
// .y = float bits of the routing factor.
__device__ int2 g_work[T_TOK];

__global__ __launch_bounds__(256) void init_work_kernel() {
    int t = blockIdx.x * 256 + threadIdx.x;
    if (t < T_TOK) g_work[t] = make_int2(-1, __float_as_int(1.0f));
}

__global__ __launch_bounds__(256) void build_work_kernel(
    const int* __restrict__ scatter_idx,        // [EC]
    const float* __restrict__ route_prob_max)   // [T]
{
    int i = blockIdx.x * 256 + threadIdx.x;
    if (i >= EC_ROWS) return;
    int r = scatter_idx[i];
    if (r < T_TOK) {
        g_work[r] = make_int2(i, __float_as_int(route_prob_max[r]));
    }
}

// Gather kernel: 2 output token rows per block, 128 threads per row.
// Each thread moves 4 float4 (64 B) of its row -> MLP=4, fully coalesced.
// Output writes are perfectly sequential across blocks.
__global__ __launch_bounds__(256) void moe_gather_kernel(
    const float* __restrict__ expert_outputs,   // [EC, D]
    const float* __restrict__ x,                // [T, D]
    const unsigned char* __restrict__ dropped,  // [T] bool
    float* __restrict__ out)                    // [T, D]
{
    const int tid  = threadIdx.x;
    const int half = tid >> 7;                  // 0 or 1: which row of the pair
    const int lane = tid & 127;
    const int t    = blockIdx.x * 2 + half;

    const int2 w = g_work[t];

    float4* __restrict__ dst4 =
        reinterpret_cast<float4*>(out + (size_t)t * D_DIM);

    const float4* __restrict__ src4;
    float factor;

    if (w.x >= 0) {
        // Kept token: scatter source row, scale by routing prob.
        src4   = reinterpret_cast<const float4*>(expert_outputs + (size_t)w.x * D_DIM);
        factor = __int_as_float(w.y);
    } else if (dropped[t]) {
        // Dropped token: pass x through, factor 1.
        src4   = reinterpret_cast<const float4*>(x + (size_t)t * D_DIM);
        factor = 1.0f;
    } else {
        // Never scattered, not dropped (empty set in this data, but match
        // reference exactly: buf stays 0, 0 * factor = 0).
        const float4 z = make_float4(0.f, 0.f, 0.f, 0.f);
        #pragma unroll
        for (int k = 0; k < 4; k++) __stcs(&dst4[lane + k * 128], z);
        return;
    }

    float4 v0 = __ldcs(&src4[lane]);
    float4 v1 = __ldcs(&src4[lane + 128]);
    float4 v2 = __ldcs(&src4[lane + 256]);
    float4 v3 = __ldcs(&src4[lane + 384]);

    v0.x *= factor; v0.y *= factor; v0.z *= factor; v0.w *= factor;
    v1.x *= factor; v1.y *= factor; v1.z *= factor; v1.w *= factor;
    v2.x *= factor; v2.y *= factor; v2.z *= factor; v2.w *= factor;
    v3.x *= factor; v3.y *= factor; v3.z *= factor; v3.w *= factor;

    __stcs(&dst4[lane],       v0);
    __stcs(&dst4[lane + 128], v1);
    __stcs(&dst4[lane + 256], v2);
    __stcs(&dst4[lane + 384], v3);
}

extern "C" void kernel_launch(void* const* d_in, const int* in_sizes, int n_in,
                              void* d_out, int out_size) {
    const float*         expert_outputs = (const float*)d_in[0];
    const float*         x              = (const float*)d_in[1];
    const float*         route_prob_max = (const float*)d_in[2];
    const int*           scatter_idx    = (const int*)d_in[3];
    const unsigned char* dropped        = (const unsigned char*)d_in[4];
    float* out = (float*)d_out;

    init_work_kernel<<<T_TOK / 256, 256>>>();
    build_work_kernel<<<EC_ROWS / 256, 256>>>(scatter_idx, route_prob_max);
    moe_gather_kernel<<<T_TOK / 2, 256>>>(expert_outputs, x, dropped, out);
}